// round 2
// baseline (speedup 1.0000x reference)
#include <cuda_runtime.h>
#include <cuda_fp16.h>
#include <cstdint>

#define NTOK 8192
#define CDIM 768
#define HDIM 3072
#define H2DIM 6144
#define NEXP 16
#define NGRP 17
#define TOPK 4
#define CAP 8192

// ---------------- scratch (static __device__, no allocs) ----------------
__device__ __half g_x16[(size_t)NTOK * CDIM];                 // 12.6 MB
__device__ __half g_wfc[(size_t)NGRP * CDIM * H2DIM];         // 160 MB (experts 0..15, shared at 16)
__device__ __half g_wpj[(size_t)NGRP * HDIM * CDIM];          // 80 MB
__device__ __half g_hid[(size_t)NGRP * CAP * HDIM];           // 856 MB
__device__ int   g_cnt[NGRP];
__device__ int   g_tok[NGRP * CAP];
__device__ float g_wt[NGRP * CAP];

// ---------------- small kernels ----------------
__global__ void init_kernel() {
    int i = threadIdx.x;
    if (i < NGRP) g_cnt[i] = (i == NEXP) ? NTOK : 0;
}

__global__ void cvt_kernel(const float4* __restrict__ src, long n4, int target, long dstOff) {
    __half* dst = (target == 0) ? g_x16 : (target == 1) ? g_wfc : g_wpj;
    dst += dstOff;
    long i = (long)blockIdx.x * blockDim.x + threadIdx.x;
    long stride = (long)gridDim.x * blockDim.x;
    for (; i < n4; i += stride) {
        float4 v = src[i];
        __half2* d2 = reinterpret_cast<__half2*>(dst + i * 4);
        d2[0] = __floats2half2_rn(v.x, v.y);
        d2[1] = __floats2half2_rn(v.z, v.w);
    }
}

// one warp per token: logits, sigmoid, top-4, normalize, fill routing lists
__global__ void gate_kernel(const float* __restrict__ x,
                            const float* __restrict__ wg,
                            const float* __restrict__ bias) {
    int warp = threadIdx.x >> 5, lane = threadIdx.x & 31;
    int n = blockIdx.x * 8 + warp;
    if (n >= NTOK) return;
    const float* xr = x + (size_t)n * CDIM;
    float p[NEXP];
#pragma unroll
    for (int e = 0; e < NEXP; e++) p[e] = 0.f;
    for (int c = lane; c < CDIM; c += 32) {
        float xv = xr[c];
        const float4* w4 = reinterpret_cast<const float4*>(wg + (size_t)c * NEXP);
#pragma unroll
        for (int q = 0; q < 4; q++) {
            float4 w = w4[q];
            p[4 * q + 0] += xv * w.x;
            p[4 * q + 1] += xv * w.y;
            p[4 * q + 2] += xv * w.z;
            p[4 * q + 3] += xv * w.w;
        }
    }
#pragma unroll
    for (int e = 0; e < NEXP; e++) {
        float v = p[e];
#pragma unroll
        for (int o = 16; o > 0; o >>= 1) v += __shfl_xor_sync(0xffffffffu, v, o);
        p[e] = v;
    }
    if (lane == 0) {
        float s[NEXP];
#pragma unroll
        for (int e = 0; e < NEXP; e++) s[e] = 1.f / (1.f + __expf(-(p[e] + bias[e])));
        int idx[TOPK]; float w[TOPK]; float wsum = 0.f;
        unsigned used = 0;
        for (int j = 0; j < TOPK; j++) {
            int best = 0; float bv = -1e30f;
#pragma unroll
            for (int e = 0; e < NEXP; e++) {
                bool ok = !((used >> e) & 1u);
                if (ok && s[e] > bv) { bv = s[e]; best = e; }
            }
            used |= 1u << best; idx[j] = best; w[j] = bv; wsum += bv;
        }
        float inv = 1.f / wsum;
        for (int j = 0; j < TOPK; j++) {
            int e = idx[j];
            int pos = atomicAdd(&g_cnt[e], 1);
            int slot = e * CAP + pos;
            g_tok[slot] = n;
            g_wt[slot]  = w[j] * inv;
        }
        g_tok[NEXP * CAP + n] = n;
        g_wt[NEXP * CAP + n]  = 1.0f;
    }
}

// ---------------- GEMM machinery ----------------
__device__ __forceinline__ void cp16(uint32_t dst, const void* src, int sz) {
    asm volatile("cp.async.cg.shared.global [%0], [%1], 16, %2;\n"
                 :: "r"(dst), "l"(src), "r"(sz));
}
__device__ __forceinline__ void ldsm_x4(uint32_t& r0, uint32_t& r1, uint32_t& r2, uint32_t& r3, uint32_t a) {
    asm volatile("ldmatrix.sync.aligned.m8n8.x4.shared.b16 {%0,%1,%2,%3}, [%4];"
                 : "=r"(r0), "=r"(r1), "=r"(r2), "=r"(r3) : "r"(a));
}
__device__ __forceinline__ void ldsm_x4_t(uint32_t& r0, uint32_t& r1, uint32_t& r2, uint32_t& r3, uint32_t a) {
    asm volatile("ldmatrix.sync.aligned.m8n8.x4.trans.shared.b16 {%0,%1,%2,%3}, [%4];"
                 : "=r"(r0), "=r"(r1), "=r"(r2), "=r"(r3) : "r"(a));
}
__device__ __forceinline__ void mma16816(float* c, uint32_t a0, uint32_t a1, uint32_t a2, uint32_t a3,
                                         uint32_t b0, uint32_t b1) {
    asm volatile("mma.sync.aligned.m16n8k16.row.col.f32.f16.f16.f32 "
                 "{%0,%1,%2,%3},{%4,%5,%6,%7},{%8,%9},{%0,%1,%2,%3};"
                 : "+f"(c[0]), "+f"(c[1]), "+f"(c[2]), "+f"(c[3])
                 : "r"(a0), "r"(a1), "r"(a2), "r"(a3), "r"(b0), "r"(b1));
}
__device__ __forceinline__ float silu_f(float v) { return v * (1.f / (1.f + __expf(-v))); }

// MODE 0: FC  (A = gathered x16 rows, B = wfc[g], epilogue = swiglu -> g_hid fp16)
// MODE 1: PROJ(A = g_hid rows,        B = wpj[g], epilogue = weighted atomicAdd -> out)
template <int MODE>
__global__ void __launch_bounds__(256, 1) moe_gemm(float* __restrict__ out) {
    constexpr int BM = 128, BK = 32;
    constexpr int ASTR = 40, BSTR = 136;           // halves; 80B/272B strides (16B aligned, conflict-free)
    constexpr int KSTEPS = (MODE == 0) ? (CDIM / BK) : (HDIM / BK);

    __shared__ __half As[2][BM * ASTR];
    __shared__ __half Bs[2][BK * BSTR];
    __shared__ int   s_tok[BM];
    __shared__ float s_wt[BM];

    const int g   = blockIdx.z;
    const int cnt = g_cnt[g];
    const int m0  = blockIdx.x * BM;
    if (m0 >= cnt) return;
    const int n0 = (MODE == 0) ? blockIdx.y * 64 : blockIdx.y * 128;

    const int tid = threadIdx.x, lane = tid & 31, warp = tid >> 5;

    if (tid < BM) {
        int r = m0 + tid;
        if (r < cnt) { s_tok[tid] = g_tok[g * CAP + r]; s_wt[tid] = g_wt[g * CAP + r]; }
        else         { s_tok[tid] = -1;                 s_wt[tid] = 0.f; }
    }
    __syncthreads();

    auto load_stage = [&](int buf, int k0) {
        uint32_t abase = (uint32_t)__cvta_generic_to_shared(&As[buf][0]);
        uint32_t bbase = (uint32_t)__cvta_generic_to_shared(&Bs[buf][0]);
#pragma unroll
        for (int i = 0; i < 2; i++) {                 // A: 512 x 16B chunks
            int c = tid + 256 * i;
            int row = c >> 2, seg = c & 3;
            uint32_t dst = abase + (uint32_t)(row * ASTR + seg * 8) * 2;
            const __half* src; int sz;
            if (MODE == 0) {
                int tok = s_tok[row];
                sz = (tok >= 0) ? 16 : 0;
                src = g_x16 + ((tok >= 0) ? ((size_t)tok * CDIM + k0 + seg * 8) : (size_t)0);
            } else {
                bool v = s_tok[row] >= 0;
                sz = v ? 16 : 0;
                src = g_hid + ((size_t)(g * CAP + m0 + row) * HDIM + k0 + seg * 8);
                if (!v) src = g_hid;
            }
            cp16(dst, src, sz);
        }
#pragma unroll
        for (int i = 0; i < 2; i++) {                 // B: 512 x 16B chunks
            int c = tid + 256 * i;
            int k = c >> 4, seg = c & 15;
            uint32_t dst = bbase + (uint32_t)(k * BSTR + seg * 8) * 2;
            const __half* src;
            if (MODE == 0) {
                int j = (seg < 8) ? (n0 + seg * 8) : (HDIM + n0 + (seg - 8) * 8);
                src = g_wfc + (size_t)g * CDIM * H2DIM + (size_t)(k0 + k) * H2DIM + j;
            } else {
                src = g_wpj + (size_t)g * HDIM * CDIM + (size_t)(k0 + k) * CDIM + n0 + seg * 8;
            }
            cp16(dst, src, 16);
        }
    };

    float acc[16][4];
#pragma unroll
    for (int i = 0; i < 16; i++)
#pragma unroll
        for (int j = 0; j < 4; j++) acc[i][j] = 0.f;

    load_stage(0, 0);
    asm volatile("cp.async.commit_group;\n");

    const int wm = warp * 16;
    for (int ks = 0; ks < KSTEPS; ks++) {
        const int buf = ks & 1;
        asm volatile("cp.async.wait_group 0;\n");
        __syncthreads();
        if (ks + 1 < KSTEPS) { load_stage(buf ^ 1, (ks + 1) * BK); asm volatile("cp.async.commit_group;\n"); }

        uint32_t abase = (uint32_t)__cvta_generic_to_shared(&As[buf][0])
                       + (uint32_t)(((wm + (lane & 15)) * ASTR + (lane >> 4) * 8) * 2);
        uint32_t bbase = (uint32_t)__cvta_generic_to_shared(&Bs[buf][0])
                       + (uint32_t)(((lane & 15) * BSTR + (lane >> 4) * 8) * 2);
#pragma unroll
        for (int ksub = 0; ksub < 2; ksub++) {
            uint32_t a0, a1, a2, a3;
            ldsm_x4(a0, a1, a2, a3, abase + ksub * 16 * 2);
#pragma unroll
            for (int np = 0; np < 8; np++) {
                uint32_t b0, b1, b2, b3;
                ldsm_x4_t(b0, b1, b2, b3, bbase + (uint32_t)((ksub * 16 * BSTR + np * 16) * 2));
                mma16816(acc[2 * np],     a0, a1, a2, a3, b0, b1);
                mma16816(acc[2 * np + 1], a0, a1, a2, a3, b2, b3);
            }
        }
        __syncthreads();
    }

    const int rq = lane >> 2, cq = (lane & 3) * 2;
    const int r0 = wm + rq, r1 = r0 + 8;

    if (MODE == 0) {
        const bool v0 = (m0 + r0) < cnt, v1 = (m0 + r1) < cnt;
        __half* h0 = g_hid + (size_t)(g * CAP + m0 + r0) * HDIM + n0 + cq;
        __half* h1 = g_hid + (size_t)(g * CAP + m0 + r1) * HDIM + n0 + cq;
#pragma unroll
        for (int nt = 0; nt < 8; nt++) {
            float o00 = silu_f(acc[nt][0]) * acc[nt + 8][0];
            float o01 = silu_f(acc[nt][1]) * acc[nt + 8][1];
            float o10 = silu_f(acc[nt][2]) * acc[nt + 8][2];
            float o11 = silu_f(acc[nt][3]) * acc[nt + 8][3];
            if (v0) *reinterpret_cast<__half2*>(h0 + nt * 8) = __floats2half2_rn(o00, o01);
            if (v1) *reinterpret_cast<__half2*>(h1 + nt * 8) = __floats2half2_rn(o10, o11);
        }
    } else {
        int t0 = s_tok[r0], t1 = s_tok[r1];
        float w0 = s_wt[r0], w1 = s_wt[r1];
        if (t0 >= 0) {
            float* o0 = out + (size_t)t0 * CDIM + n0 + cq;
#pragma unroll
            for (int nt = 0; nt < 16; nt++) {
                atomicAdd(o0 + nt * 8,     w0 * acc[nt][0]);
                atomicAdd(o0 + nt * 8 + 1, w0 * acc[nt][1]);
            }
        }
        if (t1 >= 0) {
            float* o1 = out + (size_t)t1 * CDIM + n0 + cq;
#pragma unroll
            for (int nt = 0; nt < 16; nt++) {
                atomicAdd(o1 + nt * 8,     w1 * acc[nt][2]);
                atomicAdd(o1 + nt * 8 + 1, w1 * acc[nt][3]);
            }
        }
    }
}

// ---------------- launch ----------------
extern "C" void kernel_launch(void* const* d_in, const int* in_sizes, int n_in,
                              void* d_out, int out_size) {
    const float* x   = (const float*)d_in[0];
    const float* wsf = (const float*)d_in[1];
    const float* wsp = (const float*)d_in[2];
    const float* wef = (const float*)d_in[3];
    const float* wep = (const float*)d_in[4];
    const float* wg  = (const float*)d_in[5];
    const float* eb  = (const float*)d_in[6];
    float* out = (float*)d_out;

    cudaMemsetAsync(d_out, 0, (size_t)NTOK * CDIM * sizeof(float));
    init_kernel<<<1, 32>>>();

    cvt_kernel<<<4096, 256>>>((const float4*)x,   (long)NTOK * CDIM / 4,        0, 0);
    cvt_kernel<<<8192, 256>>>((const float4*)wef, (long)NEXP * CDIM * H2DIM / 4, 1, 0);
    cvt_kernel<<<2048, 256>>>((const float4*)wsf, (long)CDIM * H2DIM / 4,        1, (long)NEXP * CDIM * H2DIM);
    cvt_kernel<<<8192, 256>>>((const float4*)wep, (long)NEXP * HDIM * CDIM / 4,  2, 0);
    cvt_kernel<<<2048, 256>>>((const float4*)wsp, (long)HDIM * CDIM / 4,         2, (long)NEXP * HDIM * CDIM);

    gate_kernel<<<NTOK / 8, 256>>>(x, wg, eb);

    moe_gemm<0><<<dim3(CAP / 128, HDIM / 64, NGRP), 256>>>(nullptr);
    moe_gemm<1><<<dim3(CAP / 128, CDIM / 128, NGRP), 256>>>(out);
}

// round 4
// speedup vs baseline: 1.4582x; 1.4582x over previous
#include <cuda_runtime.h>
#include <cuda_fp16.h>
#include <cstdint>

#define NTOK 8192
#define CDIM 768
#define HDIM 3072
#define H2DIM 6144
#define NEXP 16
#define NGRP 17
#define TOPK 4
#define CAP 8192

// ---------------- scratch (static __device__, no allocs) ----------------
__device__ __half g_x16[(size_t)NTOK * CDIM];                   // x fp16 [N][C]
__device__ __half g_wfc16[(size_t)NGRP * CDIM * H2DIM];         // [g][c][2H]
__device__ __half g_wpj16[(size_t)NGRP * HDIM * CDIM];          // [g][h][C]
__device__ __half g_hid[(size_t)NGRP * CAP * HDIM];             // hidden per slot
__device__ float g_pout[(size_t)NGRP * CAP * CDIM];             // proj out per slot
__device__ int   g_cnt[NGRP];
__device__ int   g_tok[NGRP * CAP];                             // slot -> token
__device__ int   g_tslot[NTOK * TOPK];                          // token -> slot
__device__ float g_twt[NTOK * TOPK];                            // token -> weight

// ---------------- small kernels ----------------
__global__ void init_kernel() {
    int i = threadIdx.x;
    if (i < NGRP) g_cnt[i] = (i == NEXP) ? NTOK : 0;
}

__global__ void cvt_kernel(const float4* __restrict__ src, long n4, int target, long dstOff) {
    __half* dst = (target == 0) ? g_x16 : (target == 1) ? g_wfc16 : g_wpj16;
    dst += dstOff;
    long i = (long)blockIdx.x * blockDim.x + threadIdx.x;
    long stride = (long)gridDim.x * blockDim.x;
    for (; i < n4; i += stride) {
        float4 v = src[i];
        __half2* d2 = reinterpret_cast<__half2*>(dst + i * 4);
        d2[0] = __floats2half2_rn(v.x, v.y);
        d2[1] = __floats2half2_rn(v.z, v.w);
    }
}

// one warp per token: logits, sigmoid, top-4, normalize, fill routing lists
__global__ void gate_kernel(const float* __restrict__ x,
                            const float* __restrict__ wg,
                            const float* __restrict__ bias) {
    int warp = threadIdx.x >> 5, lane = threadIdx.x & 31;
    int n = blockIdx.x * 8 + warp;
    if (n >= NTOK) return;
    const float* xr = x + (size_t)n * CDIM;
    float p[NEXP];
#pragma unroll
    for (int e = 0; e < NEXP; e++) p[e] = 0.f;
    for (int c = lane; c < CDIM; c += 32) {
        float xv = xr[c];
        const float4* w4 = reinterpret_cast<const float4*>(wg + (size_t)c * NEXP);
#pragma unroll
        for (int q = 0; q < 4; q++) {
            float4 w = w4[q];
            p[4 * q + 0] += xv * w.x;
            p[4 * q + 1] += xv * w.y;
            p[4 * q + 2] += xv * w.z;
            p[4 * q + 3] += xv * w.w;
        }
    }
#pragma unroll
    for (int e = 0; e < NEXP; e++) {
        float v = p[e];
#pragma unroll
        for (int o = 16; o > 0; o >>= 1) v += __shfl_xor_sync(0xffffffffu, v, o);
        p[e] = v;
    }
    if (lane == 0) {
        float s[NEXP];
#pragma unroll
        for (int e = 0; e < NEXP; e++) s[e] = 1.f / (1.f + __expf(-(p[e] + bias[e])));
        int idx[TOPK]; float w[TOPK]; float wsum = 0.f;
        unsigned used = 0;
        for (int j = 0; j < TOPK; j++) {
            int best = 0; float bv = -1e30f;
#pragma unroll
            for (int e = 0; e < NEXP; e++) {
                bool ok = !((used >> e) & 1u);
                if (ok && s[e] > bv) { bv = s[e]; best = e; }
            }
            used |= 1u << best; idx[j] = best; w[j] = bv; wsum += bv;
        }
        float inv = 1.f / wsum;
        for (int j = 0; j < TOPK; j++) {
            int e = idx[j];
            int pos = atomicAdd(&g_cnt[e], 1);
            int slot = e * CAP + pos;
            g_tok[slot] = n;
            g_tslot[n * TOPK + j] = slot;
            g_twt[n * TOPK + j]   = w[j] * inv;
        }
        g_tok[NEXP * CAP + n] = n;
    }
}

// ---------------- GEMM machinery (mma.sync path; tcgen05 rejected by compute_103 target) ----------------
__device__ __forceinline__ void cp16(uint32_t dst, const void* src, int sz) {
    asm volatile("cp.async.cg.shared.global [%0], [%1], 16, %2;\n"
                 :: "r"(dst), "l"(src), "r"(sz));
}
__device__ __forceinline__ void ldsm_x4(uint32_t& r0, uint32_t& r1, uint32_t& r2, uint32_t& r3, uint32_t a) {
    asm volatile("ldmatrix.sync.aligned.m8n8.x4.shared.b16 {%0,%1,%2,%3}, [%4];"
                 : "=r"(r0), "=r"(r1), "=r"(r2), "=r"(r3) : "r"(a));
}
__device__ __forceinline__ void ldsm_x4_t(uint32_t& r0, uint32_t& r1, uint32_t& r2, uint32_t& r3, uint32_t a) {
    asm volatile("ldmatrix.sync.aligned.m8n8.x4.trans.shared.b16 {%0,%1,%2,%3}, [%4];"
                 : "=r"(r0), "=r"(r1), "=r"(r2), "=r"(r3) : "r"(a));
}
__device__ __forceinline__ void mma16816(float* c, uint32_t a0, uint32_t a1, uint32_t a2, uint32_t a3,
                                         uint32_t b0, uint32_t b1) {
    asm volatile("mma.sync.aligned.m16n8k16.row.col.f32.f16.f16.f32 "
                 "{%0,%1,%2,%3},{%4,%5,%6,%7},{%8,%9},{%0,%1,%2,%3};"
                 : "+f"(c[0]), "+f"(c[1]), "+f"(c[2]), "+f"(c[3])
                 : "r"(a0), "r"(a1), "r"(a2), "r"(a3), "r"(b0), "r"(b1));
}
__device__ __forceinline__ float silu_f(float v) { return v * (1.f / (1.f + __expf(-v))); }

// tiles: CTA 256x128cols, warp 64x64cols (4x2 warps), BK=32, 3-stage cp.async
#define ASTR 40
#define BSTR 136
#define A_STAGE (256 * ASTR * 2)
#define B_STAGE (32 * BSTR * 2)
#define STAGE_BYTES (A_STAGE + B_STAGE)
#define NSTAGE 3
#define SMEM_SZ (1024 + NSTAGE * STAGE_BYTES)

// MODE 0: FC   A = gathered x16 rows [256 x C], B cols = 64 gate + 64 val of h-block, swiglu -> g_hid
// MODE 1: PROJ A = g_hid slot rows [256 x H],   B cols = 128 out channels,            -> g_pout
template <int MODE>
__global__ void __launch_bounds__(256, 1) moe_gemm() {
    constexpr int BM = 256, BK = 32;
    constexpr int KDIM = (MODE == 0) ? CDIM : HDIM;
    constexpr int KCH = KDIM / BK;

    extern __shared__ char smem[];
    int* s_tok = (int*)smem;
    const uint32_t sb = (uint32_t)__cvta_generic_to_shared(smem);

    const int g = blockIdx.z, m0 = blockIdx.x * BM;
    const int cnt = g_cnt[g];
    if (m0 >= cnt) return;

    const int tid = threadIdx.x, lane = tid & 31, warp = tid >> 5;

    if (MODE == 0) {
        int r = m0 + tid;
        s_tok[tid] = (r < cnt) ? g_tok[g * CAP + r] : -1;
    }
    __syncthreads();

    auto load_stage = [&](int st, int ch) {
        const int k0 = ch * BK;
        const uint32_t ab = sb + 1024 + st * STAGE_BYTES;
        const uint32_t bb = ab + A_STAGE;
#pragma unroll
        for (int i = 0; i < 4; i++) {                 // A: 256 rows x 64B (1024 chunks)
            int idx = tid + 256 * i;
            int row = idx >> 2, seg = idx & 3;
            uint32_t dst = ab + (uint32_t)(row * ASTR + seg * 8) * 2;
            if (MODE == 0) {
                int tok = s_tok[row];
                const __half* src = g_x16 + ((tok >= 0) ? (size_t)tok * CDIM + k0 + seg * 8 : (size_t)0);
                cp16(dst, src, tok >= 0 ? 16 : 0);
            } else {
                const __half* src = g_hid + (size_t)(g * CAP + m0 + row) * HDIM + k0 + seg * 8;
                cp16(dst, src, 16);
            }
        }
#pragma unroll
        for (int i = 0; i < 2; i++) {                 // B: 32 k-rows x 256B (512 chunks)
            int idx = tid + 256 * i;
            int row = idx >> 4, seg = idx & 15;
            uint32_t dst = bb + (uint32_t)(row * BSTR + seg * 8) * 2;
            const __half* src;
            if (MODE == 0) {
                int j = seg * 8;
                int col = (j < 64) ? (blockIdx.y * 64 + j) : (HDIM + blockIdx.y * 64 + (j - 64));
                src = g_wfc16 + (size_t)g * CDIM * H2DIM + (size_t)(k0 + row) * H2DIM + col;
            } else {
                src = g_wpj16 + (size_t)g * HDIM * CDIM + (size_t)(k0 + row) * CDIM + blockIdx.y * 128 + seg * 8;
            }
            cp16(dst, src, 16);
        }
        asm volatile("cp.async.commit_group;\n");
    };

    float acc[4][8][4];
#pragma unroll
    for (int a = 0; a < 4; a++)
#pragma unroll
        for (int b = 0; b < 8; b++)
#pragma unroll
            for (int q = 0; q < 4; q++) acc[a][b][q] = 0.f;

    load_stage(0, 0);
    load_stage(1, 1);

    const int wm = (warp >> 1) * 64;
    const int wn = (warp & 1) * 32;                   // FC: within 64-col gate half; PROJ: scaled by 2

    for (int ks = 0; ks < KCH; ks++) {
        asm volatile("cp.async.wait_group 1;\n");
        __syncthreads();
        if (ks + 2 < KCH) load_stage((ks + 2) % NSTAGE, ks + 2);

        const int st = ks % NSTAGE;
        const uint32_t ab = sb + 1024 + st * STAGE_BYTES;
        const uint32_t bb = ab + A_STAGE;
        const uint32_t abase = ab + (uint32_t)(((wm + (lane & 15)) * ASTR + (lane >> 4) * 8) * 2);
        const uint32_t bbase = bb + (uint32_t)(((lane & 15) * BSTR + (lane >> 4) * 8) * 2);

#pragma unroll
        for (int ksub = 0; ksub < 2; ksub++) {
            uint32_t a[4][4];
#pragma unroll
            for (int mt = 0; mt < 4; mt++)
                ldsm_x4(a[mt][0], a[mt][1], a[mt][2], a[mt][3],
                        abase + (uint32_t)((mt * 16 * ASTR + ksub * 16) * 2));
#pragma unroll
            for (int half = 0; half < 2; half++) {    // FC: gate/val halves. PROJ: two 32-col blocks
#pragma unroll
                for (int q = 0; q < 2; q++) {
                    int col = (MODE == 0) ? (half * 64 + wn + q * 16)
                                          : ((warp & 1) * 64 + half * 32 + q * 16);
                    uint32_t b0, b1, b2, b3;
                    ldsm_x4_t(b0, b1, b2, b3, bbase + (uint32_t)((ksub * 16 * BSTR + col) * 2));
                    int jb = half * 4 + q * 2;
#pragma unroll
                    for (int mt = 0; mt < 4; mt++) {
                        mma16816(acc[mt][jb],     a[mt][0], a[mt][1], a[mt][2], a[mt][3], b0, b1);
                        mma16816(acc[mt][jb + 1], a[mt][0], a[mt][1], a[mt][2], a[mt][3], b2, b3);
                    }
                }
            }
        }
        __syncthreads();
    }
    asm volatile("cp.async.wait_group 0;\n");

    // ---------------- epilogue ----------------
    const int rq = lane >> 2, cq = (lane & 3) * 2;

    if (MODE == 0) {
#pragma unroll
        for (int mt = 0; mt < 4; mt++) {
            int r0 = wm + mt * 16 + rq;
            __half* h0 = g_hid + (size_t)(g * CAP + m0 + r0) * HDIM + blockIdx.y * 64 + wn + cq;
            __half* h1 = h0 + 8 * (size_t)HDIM;
#pragma unroll
            for (int j = 0; j < 4; j++) {
                float ga0 = acc[mt][j][0],     ga1 = acc[mt][j][1];
                float va0 = acc[mt][j + 4][0], va1 = acc[mt][j + 4][1];
                float gb0 = acc[mt][j][2],     gb1 = acc[mt][j][3];
                float vb0 = acc[mt][j + 4][2], vb1 = acc[mt][j + 4][3];
                *reinterpret_cast<__half2*>(h0 + j * 8) =
                    __floats2half2_rn(silu_f(ga0) * va0, silu_f(ga1) * va1);
                *reinterpret_cast<__half2*>(h1 + j * 8) =
                    __floats2half2_rn(silu_f(gb0) * vb0, silu_f(gb1) * vb1);
            }
        }
    } else {
        const int cw = (warp & 1) * 64;
#pragma unroll
        for (int mt = 0; mt < 4; mt++) {
            int r0 = wm + mt * 16 + rq;
            float* o0 = g_pout + (size_t)(g * CAP + m0 + r0) * CDIM + blockIdx.y * 128 + cw + cq;
            float* o1 = o0 + 8 * (size_t)CDIM;
#pragma unroll
            for (int j = 0; j < 8; j++) {
                *reinterpret_cast<float2*>(o0 + j * 8) = make_float2(acc[mt][j][0], acc[mt][j][1]);
                *reinterpret_cast<float2*>(o1 + j * 8) = make_float2(acc[mt][j][2], acc[mt][j][3]);
            }
        }
    }
}

// ---------------- combine: out = shared + sum_j w_j * pout[slot_j] ----------------
__global__ void combine_kernel(float* __restrict__ out) {
    int idx = blockIdx.x * 256 + threadIdx.x;       // one float4 per thread
    int n = idx / (CDIM / 4), c4 = idx % (CDIM / 4);
    const float4* p4 = reinterpret_cast<const float4*>(g_pout);
    float4 a = p4[(size_t)(NEXP * CAP + n) * (CDIM / 4) + c4];
#pragma unroll
    for (int j = 0; j < TOPK; j++) {
        int slot = g_tslot[n * TOPK + j];
        float w = g_twt[n * TOPK + j];
        float4 v = p4[(size_t)slot * (CDIM / 4) + c4];
        a.x += w * v.x; a.y += w * v.y; a.z += w * v.z; a.w += w * v.w;
    }
    reinterpret_cast<float4*>(out)[idx] = a;
}

// ---------------- launch ----------------
extern "C" void kernel_launch(void* const* d_in, const int* in_sizes, int n_in,
                              void* d_out, int out_size) {
    const float* x   = (const float*)d_in[0];
    const float* wsf = (const float*)d_in[1];
    const float* wsp = (const float*)d_in[2];
    const float* wef = (const float*)d_in[3];
    const float* wep = (const float*)d_in[4];
    const float* wg  = (const float*)d_in[5];
    const float* eb  = (const float*)d_in[6];
    float* out = (float*)d_out;

    cudaFuncSetAttribute(moe_gemm<0>, cudaFuncAttributeMaxDynamicSharedMemorySize, SMEM_SZ);
    cudaFuncSetAttribute(moe_gemm<1>, cudaFuncAttributeMaxDynamicSharedMemorySize, SMEM_SZ);

    init_kernel<<<1, 32>>>();

    cvt_kernel<<<4096, 256>>>((const float4*)x,   (long)NTOK * CDIM / 4,         0, 0);
    cvt_kernel<<<8192, 256>>>((const float4*)wef, (long)NEXP * CDIM * H2DIM / 4, 1, 0);
    cvt_kernel<<<2048, 256>>>((const float4*)wsf, (long)CDIM * H2DIM / 4,        1, (long)NEXP * CDIM * H2DIM);
    cvt_kernel<<<8192, 256>>>((const float4*)wep, (long)NEXP * HDIM * CDIM / 4,  2, 0);
    cvt_kernel<<<2048, 256>>>((const float4*)wsp, (long)HDIM * CDIM / 4,         2, (long)NEXP * HDIM * CDIM);

    gate_kernel<<<NTOK / 8, 256>>>(x, wg, eb);

    moe_gemm<0><<<dim3(CAP / 256, HDIM / 64, NGRP), 256, SMEM_SZ>>>();
    moe_gemm<1><<<dim3(CAP / 256, CDIM / 128, NGRP), 256, SMEM_SZ>>>();

    combine_kernel<<<NTOK * CDIM / 4 / 256, 256>>>(out);
}

// round 5
// speedup vs baseline: 1.6101x; 1.1042x over previous
#include <cuda_runtime.h>
#include <cuda_fp16.h>
#include <cstdint>

#define NTOK 8192
#define CDIM 768
#define HDIM 3072
#define H2DIM 6144
#define NEXP 16
#define NGRP 17
#define TOPK 4
#define CAP 8192

// ---------------- scratch (static __device__, no allocs) ----------------
__device__ __half g_x16[(size_t)NTOK * CDIM];                   // x fp16 [N][C]
__device__ __half g_wfc16[(size_t)NGRP * CDIM * H2DIM];         // [g][c][2H]
__device__ __half g_wpj16[(size_t)NGRP * HDIM * CDIM];          // [g][h][C]
__device__ __half g_hid[(size_t)NGRP * CAP * HDIM];             // hidden per slot
__device__ __half g_pout[(size_t)NGRP * CAP * CDIM];            // proj out per slot (fp16)
__device__ int   g_cnt[NGRP];
__device__ int   g_tok[NGRP * CAP];                             // slot -> token
__device__ int   g_tslot[NTOK * TOPK];                          // token -> slot
__device__ float g_twt[NTOK * TOPK];                            // token -> weight

// ---------------- small kernels ----------------
__global__ void init_kernel() {
    int i = threadIdx.x;
    if (i < NGRP) g_cnt[i] = (i == NEXP) ? NTOK : 0;
}

__global__ void cvt_kernel(const float4* __restrict__ src, long n4, int target, long dstOff) {
    __half* dst = (target == 0) ? g_x16 : (target == 1) ? g_wfc16 : g_wpj16;
    dst += dstOff;
    long i = (long)blockIdx.x * blockDim.x + threadIdx.x;
    long stride = (long)gridDim.x * blockDim.x;
    for (; i < n4; i += stride) {
        float4 v = src[i];
        __half2* d2 = reinterpret_cast<__half2*>(dst + i * 4);
        d2[0] = __floats2half2_rn(v.x, v.y);
        d2[1] = __floats2half2_rn(v.z, v.w);
    }
}

// one warp per token: logits, sigmoid, top-4, normalize, fill routing lists
__global__ void gate_kernel(const float* __restrict__ x,
                            const float* __restrict__ wg,
                            const float* __restrict__ bias) {
    int warp = threadIdx.x >> 5, lane = threadIdx.x & 31;
    int n = blockIdx.x * 8 + warp;
    if (n >= NTOK) return;
    const float* xr = x + (size_t)n * CDIM;
    float p[NEXP];
#pragma unroll
    for (int e = 0; e < NEXP; e++) p[e] = 0.f;
    for (int c = lane; c < CDIM; c += 32) {
        float xv = xr[c];
        const float4* w4 = reinterpret_cast<const float4*>(wg + (size_t)c * NEXP);
#pragma unroll
        for (int q = 0; q < 4; q++) {
            float4 w = w4[q];
            p[4 * q + 0] += xv * w.x;
            p[4 * q + 1] += xv * w.y;
            p[4 * q + 2] += xv * w.z;
            p[4 * q + 3] += xv * w.w;
        }
    }
#pragma unroll
    for (int e = 0; e < NEXP; e++) {
        float v = p[e];
#pragma unroll
        for (int o = 16; o > 0; o >>= 1) v += __shfl_xor_sync(0xffffffffu, v, o);
        p[e] = v;
    }
    if (lane == 0) {
        float s[NEXP];
#pragma unroll
        for (int e = 0; e < NEXP; e++) s[e] = 1.f / (1.f + __expf(-(p[e] + bias[e])));
        int idx[TOPK]; float w[TOPK]; float wsum = 0.f;
        unsigned used = 0;
        for (int j = 0; j < TOPK; j++) {
            int best = 0; float bv = -1e30f;
#pragma unroll
            for (int e = 0; e < NEXP; e++) {
                bool ok = !((used >> e) & 1u);
                if (ok && s[e] > bv) { bv = s[e]; best = e; }
            }
            used |= 1u << best; idx[j] = best; w[j] = bv; wsum += bv;
        }
        float inv = 1.f / wsum;
        for (int j = 0; j < TOPK; j++) {
            int e = idx[j];
            int pos = atomicAdd(&g_cnt[e], 1);
            int slot = e * CAP + pos;
            g_tok[slot] = n;
            g_tslot[n * TOPK + j] = slot;
            g_twt[n * TOPK + j]   = w[j] * inv;
        }
        g_tok[NEXP * CAP + n] = n;
    }
}

// ---------------- GEMM machinery (mma.sync; tcgen05 rejected by compute_103 target) ----------------
__device__ __forceinline__ void cp16(uint32_t dst, const void* src, int sz) {
    asm volatile("cp.async.cg.shared.global [%0], [%1], 16, %2;\n"
                 :: "r"(dst), "l"(src), "r"(sz));
}
__device__ __forceinline__ void ldsm_x4(uint32_t& r0, uint32_t& r1, uint32_t& r2, uint32_t& r3, uint32_t a) {
    asm volatile("ldmatrix.sync.aligned.m8n8.x4.shared.b16 {%0,%1,%2,%3}, [%4];"
                 : "=r"(r0), "=r"(r1), "=r"(r2), "=r"(r3) : "r"(a));
}
__device__ __forceinline__ void ldsm_x4_t(uint32_t& r0, uint32_t& r1, uint32_t& r2, uint32_t& r3, uint32_t a) {
    asm volatile("ldmatrix.sync.aligned.m8n8.x4.trans.shared.b16 {%0,%1,%2,%3}, [%4];"
                 : "=r"(r0), "=r"(r1), "=r"(r2), "=r"(r3) : "r"(a));
}
__device__ __forceinline__ void mma16816(float* c, uint32_t a0, uint32_t a1, uint32_t a2, uint32_t a3,
                                         uint32_t b0, uint32_t b1) {
    asm volatile("mma.sync.aligned.m16n8k16.row.col.f32.f16.f16.f32 "
                 "{%0,%1,%2,%3},{%4,%5,%6,%7},{%8,%9},{%0,%1,%2,%3};"
                 : "+f"(c[0]), "+f"(c[1]), "+f"(c[2]), "+f"(c[3])
                 : "r"(a0), "r"(a1), "r"(a2), "r"(a3), "r"(b0), "r"(b1));
}
__device__ __forceinline__ float silu_f(float v) { return v * (1.f / (1.f + __expf(-v))); }

// tiles: CTA 256 rows x 128 cols, warp 64x64 (4x2 warps), BK=64, 3-stage cp.async
#define ASTR 72
#define BSTR 136
#define A_STAGE (256 * ASTR * 2)
#define B_STAGE (64 * BSTR * 2)
#define STAGE_BYTES (A_STAGE + B_STAGE)
#define NSTAGE 3
#define SMEM_SZ (1024 + NSTAGE * STAGE_BYTES)

// MODE 0: FC   A = gathered x16 rows [256 x C], B cols = 64 gate + 64 val of h-block, swiglu -> g_hid
// MODE 1: PROJ A = g_hid slot rows [256 x H],   B cols = 128 out channels,            -> g_pout (fp16)
template <int MODE>
__global__ void __launch_bounds__(256, 1) moe_gemm() {
    constexpr int BM = 256, BK = 64;
    constexpr int KDIM = (MODE == 0) ? CDIM : HDIM;
    constexpr int KCH = KDIM / BK;

    extern __shared__ char smem[];
    int* s_tok = (int*)smem;
    const uint32_t sb = (uint32_t)__cvta_generic_to_shared(smem);

    const int g = blockIdx.z, m0 = blockIdx.x * BM;
    const int cnt = g_cnt[g];
    if (m0 >= cnt) return;

    const int tid = threadIdx.x, lane = tid & 31, warp = tid >> 5;

    if (MODE == 0) {
        int r = m0 + tid;
        s_tok[tid] = (r < cnt) ? g_tok[g * CAP + r] : -1;
    }
    __syncthreads();

    auto load_stage = [&](int st, int ch) {
        const int k0 = ch * BK;
        const uint32_t ab = sb + 1024 + st * STAGE_BYTES;
        const uint32_t bb = ab + A_STAGE;
#pragma unroll
        for (int i = 0; i < 8; i++) {                 // A: 256 rows x 128B (2048 chunks)
            int idx = tid + 256 * i;
            int row = idx >> 3, seg = idx & 7;
            uint32_t dst = ab + (uint32_t)(row * ASTR + seg * 8) * 2;
            if (MODE == 0) {
                int tok = s_tok[row];
                const __half* src = g_x16 + ((tok >= 0) ? (size_t)tok * CDIM + k0 + seg * 8 : (size_t)0);
                cp16(dst, src, tok >= 0 ? 16 : 0);
            } else {
                const __half* src = g_hid + (size_t)(g * CAP + m0 + row) * HDIM + k0 + seg * 8;
                cp16(dst, src, 16);
            }
        }
#pragma unroll
        for (int i = 0; i < 4; i++) {                 // B: 64 k-rows x 256B (1024 chunks)
            int idx = tid + 256 * i;
            int row = idx >> 4, seg = idx & 15;
            uint32_t dst = bb + (uint32_t)(row * BSTR + seg * 8) * 2;
            const __half* src;
            if (MODE == 0) {
                int j = seg * 8;
                int col = (j < 64) ? (blockIdx.y * 64 + j) : (HDIM + blockIdx.y * 64 + (j - 64));
                src = g_wfc16 + (size_t)g * CDIM * H2DIM + (size_t)(k0 + row) * H2DIM + col;
            } else {
                src = g_wpj16 + (size_t)g * HDIM * CDIM + (size_t)(k0 + row) * CDIM + blockIdx.y * 128 + seg * 8;
            }
            cp16(dst, src, 16);
        }
        asm volatile("cp.async.commit_group;\n");
    };

    float acc[4][8][4];
#pragma unroll
    for (int a = 0; a < 4; a++)
#pragma unroll
        for (int b = 0; b < 8; b++)
#pragma unroll
            for (int q = 0; q < 4; q++) acc[a][b][q] = 0.f;

    load_stage(0, 0);
    load_stage(1, 1);

    const int wm = (warp >> 1) * 64;
    const int wn = (warp & 1) * 32;

    for (int ks = 0; ks < KCH; ks++) {
        if (ks < KCH - 1) asm volatile("cp.async.wait_group 1;\n");
        else              asm volatile("cp.async.wait_group 0;\n");
        __syncthreads();
        if (ks + 2 < KCH) load_stage((ks + 2) % NSTAGE, ks + 2);

        const int st = ks % NSTAGE;
        const uint32_t ab = sb + 1024 + st * STAGE_BYTES;
        const uint32_t bb = ab + A_STAGE;
        const uint32_t abase = ab + (uint32_t)(((wm + (lane & 15)) * ASTR + (lane >> 4) * 8) * 2);
        const uint32_t bbase = bb + (uint32_t)(((lane & 15) * BSTR + (lane >> 4) * 8) * 2);

#pragma unroll
        for (int ksub = 0; ksub < 4; ksub++) {
            uint32_t a[4][4];
#pragma unroll
            for (int mt = 0; mt < 4; mt++)
                ldsm_x4(a[mt][0], a[mt][1], a[mt][2], a[mt][3],
                        abase + (uint32_t)((mt * 16 * ASTR + ksub * 16) * 2));
#pragma unroll
            for (int half = 0; half < 2; half++) {
#pragma unroll
                for (int q = 0; q < 2; q++) {
                    int col = (MODE == 0) ? (half * 64 + wn + q * 16)
                                          : ((warp & 1) * 64 + half * 32 + q * 16);
                    uint32_t b0, b1, b2, b3;
                    ldsm_x4_t(b0, b1, b2, b3, bbase + (uint32_t)((ksub * 16 * BSTR + col) * 2));
                    int jb = half * 4 + q * 2;
#pragma unroll
                    for (int mt = 0; mt < 4; mt++) {
                        mma16816(acc[mt][jb],     a[mt][0], a[mt][1], a[mt][2], a[mt][3], b0, b1);
                        mma16816(acc[mt][jb + 1], a[mt][0], a[mt][1], a[mt][2], a[mt][3], b2, b3);
                    }
                }
            }
        }
        // no trailing __syncthreads: with 3 stages the written stage (ks+2)%3
        // differs from every stage any warp between top-sync(ks) and top-sync(ks+1) can read.
    }

    // ---------------- epilogue ----------------
    const int rq = lane >> 2, cq = (lane & 3) * 2;

    if (MODE == 0) {
#pragma unroll
        for (int mt = 0; mt < 4; mt++) {
            int r0 = wm + mt * 16 + rq;
            __half* h0 = g_hid + (size_t)(g * CAP + m0 + r0) * HDIM + blockIdx.y * 64 + wn + cq;
            __half* h1 = h0 + 8 * (size_t)HDIM;
#pragma unroll
            for (int j = 0; j < 4; j++) {
                float ga0 = acc[mt][j][0],     ga1 = acc[mt][j][1];
                float va0 = acc[mt][j + 4][0], va1 = acc[mt][j + 4][1];
                float gb0 = acc[mt][j][2],     gb1 = acc[mt][j][3];
                float vb0 = acc[mt][j + 4][2], vb1 = acc[mt][j + 4][3];
                *reinterpret_cast<__half2*>(h0 + j * 8) =
                    __floats2half2_rn(silu_f(ga0) * va0, silu_f(ga1) * va1);
                *reinterpret_cast<__half2*>(h1 + j * 8) =
                    __floats2half2_rn(silu_f(gb0) * vb0, silu_f(gb1) * vb1);
            }
        }
    } else {
        const int cw = (warp & 1) * 64;
#pragma unroll
        for (int mt = 0; mt < 4; mt++) {
            int r0 = wm + mt * 16 + rq;
            __half* o0 = g_pout + (size_t)(g * CAP + m0 + r0) * CDIM + blockIdx.y * 128 + cw + cq;
            __half* o1 = o0 + 8 * (size_t)CDIM;
#pragma unroll
            for (int j = 0; j < 8; j++) {
                *reinterpret_cast<__half2*>(o0 + j * 8) = __floats2half2_rn(acc[mt][j][0], acc[mt][j][1]);
                *reinterpret_cast<__half2*>(o1 + j * 8) = __floats2half2_rn(acc[mt][j][2], acc[mt][j][3]);
            }
        }
    }
}

// ---------------- combine: out = shared + sum_j w_j * pout[slot_j] ----------------
__global__ void combine_kernel(float* __restrict__ out) {
    int idx = blockIdx.x * 256 + threadIdx.x;       // 4 outputs per thread
    int n = idx / (CDIM / 4), c4 = idx % (CDIM / 4);
    const uint2* p = reinterpret_cast<const uint2*>(g_pout);   // 4 halves per uint2
    uint2 sv = p[((size_t)NEXP * CAP + n) * (CDIM / 4) + c4];
    float2 a01 = __half22float2(*reinterpret_cast<__half2*>(&sv.x));
    float2 a23 = __half22float2(*reinterpret_cast<__half2*>(&sv.y));
#pragma unroll
    for (int j = 0; j < TOPK; j++) {
        int slot = g_tslot[n * TOPK + j];
        float w = g_twt[n * TOPK + j];
        uint2 v = p[(size_t)slot * (CDIM / 4) + c4];
        float2 v01 = __half22float2(*reinterpret_cast<__half2*>(&v.x));
        float2 v23 = __half22float2(*reinterpret_cast<__half2*>(&v.y));
        a01.x += w * v01.x; a01.y += w * v01.y;
        a23.x += w * v23.x; a23.y += w * v23.y;
    }
    float4 r = make_float4(a01.x, a01.y, a23.x, a23.y);
    reinterpret_cast<float4*>(out)[idx] = r;
}

// ---------------- launch ----------------
extern "C" void kernel_launch(void* const* d_in, const int* in_sizes, int n_in,
                              void* d_out, int out_size) {
    const float* x   = (const float*)d_in[0];
    const float* wsf = (const float*)d_in[1];
    const float* wsp = (const float*)d_in[2];
    const float* wef = (const float*)d_in[3];
    const float* wep = (const float*)d_in[4];
    const float* wg  = (const float*)d_in[5];
    const float* eb  = (const float*)d_in[6];
    float* out = (float*)d_out;

    cudaFuncSetAttribute(moe_gemm<0>, cudaFuncAttributeMaxDynamicSharedMemorySize, SMEM_SZ);
    cudaFuncSetAttribute(moe_gemm<1>, cudaFuncAttributeMaxDynamicSharedMemorySize, SMEM_SZ);

    // launch order arranged so ncu (-s 5 -c 1) profiles moe_gemm<0> (6th launch)
    init_kernel<<<1, 32>>>();                                                          // 1
    gate_kernel<<<NTOK / 8, 256>>>(x, wg, eb);                                         // 2
    cvt_kernel<<<4096, 256>>>((const float4*)x,   (long)NTOK * CDIM / 4,         0, 0);// 3
    cvt_kernel<<<8192, 256>>>((const float4*)wef, (long)NEXP * CDIM * H2DIM / 4, 1, 0);// 4
    cvt_kernel<<<2048, 256>>>((const float4*)wsf, (long)CDIM * H2DIM / 4,        1, (long)NEXP * CDIM * H2DIM); // 5

    moe_gemm<0><<<dim3(CAP / 256, HDIM / 64, NGRP), 256, SMEM_SZ>>>();                 // 6  <-- profiled

    cvt_kernel<<<8192, 256>>>((const float4*)wep, (long)NEXP * HDIM * CDIM / 4,  2, 0);// 7
    cvt_kernel<<<2048, 256>>>((const float4*)wsp, (long)HDIM * CDIM / 4,         2, (long)NEXP * HDIM * CDIM); // 8

    moe_gemm<1><<<dim3(CAP / 256, CDIM / 128, NGRP), 256, SMEM_SZ>>>();                // 9

    combine_kernel<<<NTOK * CDIM / 4 / 256, 256>>>(out);                               // 10
}

// round 7
// speedup vs baseline: 1.9717x; 1.2245x over previous
#include <cuda_runtime.h>
#include <cuda_fp16.h>
#include <cstdint>

#define NTOK 8192
#define CDIM 768
#define HDIM 3072
#define H2DIM 6144
#define NEXP 16
#define NGRP 17
#define TOPK 4
#define CAP 8192

// ---------------- scratch (static __device__, no allocs) ----------------
__device__ __half g_x16[(size_t)NTOK * CDIM];                   // x fp16 [N][C]
__device__ __half g_wfc16[(size_t)NGRP * CDIM * H2DIM];         // [g][c][2H]
__device__ __half g_wpj16[(size_t)NGRP * HDIM * CDIM];          // [g][h][C]
__device__ __half g_hid[(size_t)NGRP * CAP * HDIM];             // hidden per slot
__device__ __half g_pout[(size_t)NGRP * CAP * CDIM];            // proj out per slot (fp16)
__device__ int   g_cnt[NGRP];
__device__ int   g_tok[NGRP * CAP];                             // slot -> token
__device__ int   g_tslot[NTOK * TOPK];                          // token -> slot
__device__ float g_twt[NTOK * TOPK];                            // token -> weight

// ---------------- fused gate + x fp32->fp16 convert ----------------
// one warp per token: convert row to fp16, logits, sigmoid, top-4, fill lists
__global__ void gate_kernel(const float* __restrict__ x,
                            const float* __restrict__ wg,
                            const float* __restrict__ bias) {
    int warp = threadIdx.x >> 5, lane = threadIdx.x & 31;
    int n = blockIdx.x * 8 + warp;
    if (n >= NTOK) return;
    const float* xr = x + (size_t)n * CDIM;
    __half* xh = g_x16 + (size_t)n * CDIM;
    float p[NEXP];
#pragma unroll
    for (int e = 0; e < NEXP; e++) p[e] = 0.f;
    for (int c = lane; c < CDIM; c += 32) {
        float xv = xr[c];
        xh[c] = __float2half(xv);
        const float4* w4 = reinterpret_cast<const float4*>(wg + (size_t)c * NEXP);
#pragma unroll
        for (int q = 0; q < 4; q++) {
            float4 w = w4[q];
            p[4 * q + 0] += xv * w.x;
            p[4 * q + 1] += xv * w.y;
            p[4 * q + 2] += xv * w.z;
            p[4 * q + 3] += xv * w.w;
        }
    }
#pragma unroll
    for (int e = 0; e < NEXP; e++) {
        float v = p[e];
#pragma unroll
        for (int o = 16; o > 0; o >>= 1) v += __shfl_xor_sync(0xffffffffu, v, o);
        p[e] = v;
    }
    if (lane == 0) {
        float s[NEXP];
#pragma unroll
        for (int e = 0; e < NEXP; e++) s[e] = 1.f / (1.f + __expf(-(p[e] + bias[e])));
        int idx[TOPK]; float w[TOPK]; float wsum = 0.f;
        unsigned used = 0;
        for (int j = 0; j < TOPK; j++) {
            int best = 0; float bv = -1e30f;
#pragma unroll
            for (int e = 0; e < NEXP; e++) {
                bool ok = !((used >> e) & 1u);
                if (ok && s[e] > bv) { bv = s[e]; best = e; }
            }
            used |= 1u << best; idx[j] = best; w[j] = bv; wsum += bv;
        }
        float inv = 1.f / wsum;
        for (int j = 0; j < TOPK; j++) {
            int e = idx[j];
            int pos = atomicAdd(&g_cnt[e], 1);
            int slot = e * CAP + pos;
            g_tok[slot] = n;
            g_tslot[n * TOPK + j] = slot;
            g_twt[n * TOPK + j]   = w[j] * inv;
        }
        g_tok[NEXP * CAP + n] = n;
    }
}

__global__ void cvt_kernel(const float4* __restrict__ src, long n4, int target, long dstOff) {
    __half* dst = (target == 1) ? g_wfc16 : g_wpj16;
    dst += dstOff;
    long i = (long)blockIdx.x * blockDim.x + threadIdx.x;
    long stride = (long)gridDim.x * blockDim.x;
    for (; i < n4; i += stride) {
        float4 v = src[i];
        __half2* d2 = reinterpret_cast<__half2*>(dst + i * 4);
        d2[0] = __floats2half2_rn(v.x, v.y);
        d2[1] = __floats2half2_rn(v.z, v.w);
    }
}

// ---------------- GEMM machinery (mma.sync; tcgen05 rejected by compute_103 target) ----------------
__device__ __forceinline__ void cp16(uint32_t dst, const void* src, int sz) {
    asm volatile("cp.async.cg.shared.global [%0], [%1], 16, %2;\n"
                 :: "r"(dst), "l"(src), "r"(sz));
}
__device__ __forceinline__ void ldsm_x4(uint32_t& r0, uint32_t& r1, uint32_t& r2, uint32_t& r3, uint32_t a) {
    asm volatile("ldmatrix.sync.aligned.m8n8.x4.shared.b16 {%0,%1,%2,%3}, [%4];"
                 : "=r"(r0), "=r"(r1), "=r"(r2), "=r"(r3) : "r"(a));
}
__device__ __forceinline__ void ldsm_x4_t(uint32_t& r0, uint32_t& r1, uint32_t& r2, uint32_t& r3, uint32_t a) {
    asm volatile("ldmatrix.sync.aligned.m8n8.x4.trans.shared.b16 {%0,%1,%2,%3}, [%4];"
                 : "=r"(r0), "=r"(r1), "=r"(r2), "=r"(r3) : "r"(a));
}
__device__ __forceinline__ void mma16816(float* c, uint32_t a0, uint32_t a1, uint32_t a2, uint32_t a3,
                                         uint32_t b0, uint32_t b1) {
    asm volatile("mma.sync.aligned.m16n8k16.row.col.f32.f16.f16.f32 "
                 "{%0,%1,%2,%3},{%4,%5,%6,%7},{%8,%9},{%0,%1,%2,%3};"
                 : "+f"(c[0]), "+f"(c[1]), "+f"(c[2]), "+f"(c[3])
                 : "r"(a0), "r"(a1), "r"(a2), "r"(a3), "r"(b0), "r"(b1));
}
__device__ __forceinline__ float silu_f(float v) { return v * (1.f / (1.f + __expf(-v))); }

// tiles: CTA 128 rows x 128 cols, warp 32x64 (4x2 warps), BK=64, 3-stage, 2 CTAs/SM
#define ASTR 72
#define BSTR 136
#define A_STAGE (128 * ASTR * 2)
#define B_STAGE (64 * BSTR * 2)
#define STAGE_BYTES (A_STAGE + B_STAGE)
#define NSTAGE 3
#define SMEM_SZ (1024 + NSTAGE * STAGE_BYTES)

// MODE 0: FC   A = gathered x16 rows [128 x C], B cols = 64 gate + 64 val of h-block, swiglu -> g_hid
// MODE 1: PROJ A = g_hid slot rows [128 x H],   B cols = 128 out channels,            -> g_pout (fp16)
template <int MODE>
__global__ void __launch_bounds__(256, 2) moe_gemm() {
    constexpr int BM = 128, BK = 64;
    constexpr int KDIM = (MODE == 0) ? CDIM : HDIM;
    constexpr int KCH = KDIM / BK;

    extern __shared__ char smem[];
    int* s_tok = (int*)smem;
    const uint32_t sb = (uint32_t)__cvta_generic_to_shared(smem);

    const int g = blockIdx.z, m0 = blockIdx.x * BM;
    const int cnt = (g == NEXP) ? NTOK : g_cnt[g];
    if (m0 >= cnt) return;

    const int tid = threadIdx.x, lane = tid & 31, warp = tid >> 5;

    if (MODE == 0 && tid < BM) {
        int r = m0 + tid;
        s_tok[tid] = (r < cnt) ? g_tok[g * CAP + r] : -1;
    }
    __syncthreads();

    auto load_stage = [&](int st, int ch) {
        const int k0 = ch * BK;
        const uint32_t ab = sb + 1024 + st * STAGE_BYTES;
        const uint32_t bb = ab + A_STAGE;
#pragma unroll
        for (int i = 0; i < 4; i++) {                 // A: 128 rows x 128B (1024 chunks)
            int idx = tid + 256 * i;
            int row = idx >> 3, seg = idx & 7;
            uint32_t dst = ab + (uint32_t)(row * ASTR + seg * 8) * 2;
            if (MODE == 0) {
                int tok = s_tok[row];
                const __half* src = g_x16 + ((tok >= 0) ? (size_t)tok * CDIM + k0 + seg * 8 : (size_t)0);
                cp16(dst, src, tok >= 0 ? 16 : 0);
            } else {
                const __half* src = g_hid + (size_t)(g * CAP + m0 + row) * HDIM + k0 + seg * 8;
                cp16(dst, src, 16);
            }
        }
#pragma unroll
        for (int i = 0; i < 4; i++) {                 // B: 64 k-rows x 256B (1024 chunks)
            int idx = tid + 256 * i;
            int row = idx >> 4, seg = idx & 15;
            uint32_t dst = bb + (uint32_t)(row * BSTR + seg * 8) * 2;
            const __half* src;
            if (MODE == 0) {
                int j = seg * 8;
                int col = (j < 64) ? (blockIdx.y * 64 + j) : (HDIM + blockIdx.y * 64 + (j - 64));
                src = g_wfc16 + (size_t)g * CDIM * H2DIM + (size_t)(k0 + row) * H2DIM + col;
            } else {
                src = g_wpj16 + (size_t)g * HDIM * CDIM + (size_t)(k0 + row) * CDIM + blockIdx.y * 128 + seg * 8;
            }
            cp16(dst, src, 16);
        }
        asm volatile("cp.async.commit_group;\n");
    };

    float acc[2][8][4];
#pragma unroll
    for (int a = 0; a < 2; a++)
#pragma unroll
        for (int b = 0; b < 8; b++)
#pragma unroll
            for (int q = 0; q < 4; q++) acc[a][b][q] = 0.f;

    load_stage(0, 0);
    load_stage(1, 1);

    const int wm = (warp >> 1) * 32;
    const int wn = (warp & 1) * 32;

    for (int ks = 0; ks < KCH; ks++) {
        if (ks < KCH - 1) asm volatile("cp.async.wait_group 1;\n");
        else              asm volatile("cp.async.wait_group 0;\n");
        __syncthreads();
        if (ks + 2 < KCH) load_stage((ks + 2) % NSTAGE, ks + 2);

        const int st = ks % NSTAGE;
        const uint32_t ab = sb + 1024 + st * STAGE_BYTES;
        const uint32_t bb = ab + A_STAGE;
        const uint32_t abase = ab + (uint32_t)(((wm + (lane & 15)) * ASTR + (lane >> 4) * 8) * 2);
        const uint32_t bbase = bb + (uint32_t)(((lane & 15) * BSTR + (lane >> 4) * 8) * 2);

#pragma unroll
        for (int ksub = 0; ksub < 4; ksub++) {
            uint32_t a[2][4];
#pragma unroll
            for (int mt = 0; mt < 2; mt++)
                ldsm_x4(a[mt][0], a[mt][1], a[mt][2], a[mt][3],
                        abase + (uint32_t)((mt * 16 * ASTR + ksub * 16) * 2));
#pragma unroll
            for (int half = 0; half < 2; half++) {
#pragma unroll
                for (int q = 0; q < 2; q++) {
                    int col = (MODE == 0) ? (half * 64 + wn + q * 16)
                                          : ((warp & 1) * 64 + half * 32 + q * 16);
                    uint32_t b0, b1, b2, b3;
                    ldsm_x4_t(b0, b1, b2, b3, bbase + (uint32_t)((ksub * 16 * BSTR + col) * 2));
                    int jb = half * 4 + q * 2;
#pragma unroll
                    for (int mt = 0; mt < 2; mt++) {
                        mma16816(acc[mt][jb],     a[mt][0], a[mt][1], a[mt][2], a[mt][3], b0, b1);
                        mma16816(acc[mt][jb + 1], a[mt][0], a[mt][1], a[mt][2], a[mt][3], b2, b3);
                    }
                }
            }
        }
        // no trailing __syncthreads: with 3 stages the stage written at ks (idx (ks+2)%3)
        // is distinct from any stage readable between top-sync(ks) and top-sync(ks+1).
    }

    // ---------------- epilogue ----------------
    const int rq = lane >> 2, cq = (lane & 3) * 2;

    if (MODE == 0) {
#pragma unroll
        for (int mt = 0; mt < 2; mt++) {
            int r0 = wm + mt * 16 + rq;
            __half* h0 = g_hid + (size_t)(g * CAP + m0 + r0) * HDIM + blockIdx.y * 64 + wn + cq;
            __half* h1 = h0 + 8 * (size_t)HDIM;
#pragma unroll
            for (int j = 0; j < 4; j++) {
                float ga0 = acc[mt][j][0],     ga1 = acc[mt][j][1];
                float va0 = acc[mt][j + 4][0], va1 = acc[mt][j + 4][1];
                float gb0 = acc[mt][j][2],     gb1 = acc[mt][j][3];
                float vb0 = acc[mt][j + 4][2], vb1 = acc[mt][j + 4][3];
                *reinterpret_cast<__half2*>(h0 + j * 8) =
                    __floats2half2_rn(silu_f(ga0) * va0, silu_f(ga1) * va1);
                *reinterpret_cast<__half2*>(h1 + j * 8) =
                    __floats2half2_rn(silu_f(gb0) * vb0, silu_f(gb1) * vb1);
            }
        }
    } else {
        const int cw = (warp & 1) * 64;
#pragma unroll
        for (int mt = 0; mt < 2; mt++) {
            int r0 = wm + mt * 16 + rq;
            __half* o0 = g_pout + (size_t)(g * CAP + m0 + r0) * CDIM + blockIdx.y * 128 + cw + cq;
            __half* o1 = o0 + 8 * (size_t)CDIM;
#pragma unroll
            for (int j = 0; j < 8; j++) {
                *reinterpret_cast<__half2*>(o0 + j * 8) = __floats2half2_rn(acc[mt][j][0], acc[mt][j][1]);
                *reinterpret_cast<__half2*>(o1 + j * 8) = __floats2half2_rn(acc[mt][j][2], acc[mt][j][3]);
            }
        }
    }
}

// ---------------- combine: out = shared + sum_j w_j * pout[slot_j] ----------------
__global__ void combine_kernel(float* __restrict__ out) {
    int idx = blockIdx.x * 256 + threadIdx.x;       // 4 outputs per thread
    int n = idx / (CDIM / 4), c4 = idx % (CDIM / 4);
    const uint2* p = reinterpret_cast<const uint2*>(g_pout);   // 4 halves per uint2
    uint2 sv = p[((size_t)NEXP * CAP + n) * (CDIM / 4) + c4];
    float2 a01 = __half22float2(*reinterpret_cast<__half2*>(&sv.x));
    float2 a23 = __half22float2(*reinterpret_cast<__half2*>(&sv.y));
#pragma unroll
    for (int j = 0; j < TOPK; j++) {
        int slot = g_tslot[n * TOPK + j];
        float w = g_twt[n * TOPK + j];
        uint2 v = p[(size_t)slot * (CDIM / 4) + c4];
        float2 v01 = __half22float2(*reinterpret_cast<__half2*>(&v.x));
        float2 v23 = __half22float2(*reinterpret_cast<__half2*>(&v.y));
        a01.x += w * v01.x; a01.y += w * v01.y;
        a23.x += w * v23.x; a23.y += w * v23.y;
    }
    float4 r = make_float4(a01.x, a01.y, a23.x, a23.y);
    reinterpret_cast<float4*>(out)[idx] = r;
}

// ---------------- launch ----------------
extern "C" void kernel_launch(void* const* d_in, const int* in_sizes, int n_in,
                              void* d_out, int out_size) {
    const float* x   = (const float*)d_in[0];
    const float* wsf = (const float*)d_in[1];
    const float* wsp = (const float*)d_in[2];
    const float* wef = (const float*)d_in[3];
    const float* wep = (const float*)d_in[4];
    const float* wg  = (const float*)d_in[5];
    const float* eb  = (const float*)d_in[6];
    float* out = (float*)d_out;

    cudaFuncSetAttribute(moe_gemm<0>, cudaFuncAttributeMaxDynamicSharedMemorySize, SMEM_SZ);
    cudaFuncSetAttribute(moe_gemm<1>, cudaFuncAttributeMaxDynamicSharedMemorySize, SMEM_SZ);

    // FIX: resolve the DEVICE address of g_cnt; passing the __device__ symbol
    // directly gave cudaMemsetAsync the host shadow address -> stale counters
    // -> out-of-bounds g_tok writes -> illegal memory access.
    void* cnt_ptr = nullptr;
    cudaGetSymbolAddress(&cnt_ptr, g_cnt);
    cudaMemsetAsync(cnt_ptr, 0, sizeof(int) * NGRP);

    // launch order: moe_gemm<0> is my 4th kernel => global launch idx 5 => profiled by ncu -s 5
    gate_kernel<<<NTOK / 8, 256>>>(x, wg, eb);                                         // idx2 (2 pre-launches)
    cvt_kernel<<<8192, 256>>>((const float4*)wef, (long)NEXP * CDIM * H2DIM / 4, 1, 0);// idx3
    cvt_kernel<<<2048, 256>>>((const float4*)wsf, (long)CDIM * H2DIM / 4,        1, (long)NEXP * CDIM * H2DIM); // idx4

    moe_gemm<0><<<dim3(CAP / 128, HDIM / 64, NGRP), 256, SMEM_SZ>>>();                 // idx5 <-- profiled

    cvt_kernel<<<8192, 256>>>((const float4*)wep, (long)NEXP * HDIM * CDIM / 4,  2, 0);
    cvt_kernel<<<2048, 256>>>((const float4*)wsp, (long)HDIM * CDIM / 4,         2, (long)NEXP * HDIM * CDIM);

    moe_gemm<1><<<dim3(CAP / 128, CDIM / 128, NGRP), 256, SMEM_SZ>>>();

    combine_kernel<<<NTOK * CDIM / 4 / 256, 256>>>(out);
}